// round 11
// baseline (speedup 1.0000x reference)
#include <cuda_runtime.h>
#include <cstdint>

#define Bq 4
#define T 128
#define D 300
#define D4 75            // D / 4 (float4 count per row)

// Projection partials (3-way k-split) + final q|k|v scratch
__device__ __align__(16) float g_p0[3 * Bq * T * D];
__device__ __align__(16) float g_p1[3 * Bq * T * D];
__device__ __align__(16) float g_p2[3 * Bq * T * D];
__device__ __align__(16) float g_qkv[3 * Bq * T * D];

// ---------------------------------------------------------------------------
// Kernel 1: projection GEMM, 3-way k-split (k ranges of 100), 32x64 tiles,
// 128 threads, 4x4 microtile (2 B/FMA LDS), k-chunk 32 double-buffered.
// Grid (5, 48, 3) = 720 CTAs -> ~19.5 warps/SM.
// partial[r,c] = sum_{k in third} A[r,k] * W[c,k]  (+bias in third 0)
// rows 0..511 -> query/WQ/bQ, 512..1023 -> key/WK/bK, 1024..1535 -> value/WK/bK
// ---------------------------------------------------------------------------
__global__ __launch_bounds__(128) void proj_kernel(
    const float* __restrict__ query, const float* __restrict__ key,
    const float* __restrict__ value,
    const float* __restrict__ WQ, const float* __restrict__ bQ,
    const float* __restrict__ WK, const float* __restrict__ bK)
{
    __shared__ float A_s[2][32][36];
    __shared__ float W_s[2][32][68];

    const int row0 = blockIdx.y * 32;
    const int col0 = blockIdx.x * 64;
    const int kh   = blockIdx.z;          // 0,1,2
    const int ks   = kh * 100;
    const int ke   = ks + 100;
    float* outp    = (kh == 0) ? g_p0 : (kh == 1 ? g_p1 : g_p2);

    const int tid  = threadIdx.x;
    const int tx   = tid & 15;    // 16 col groups x 4 cols
    const int ty   = tid >> 4;    // 8 row groups x 4 rows

    const int sel = row0 >> 9;    // 0: query, 1: key, 2: value
    const float* Ap = (sel == 0) ? query : (sel == 1 ? key : value);
    const float* Wp = (sel == 0) ? WQ : WK;
    const float* bp = (sel == 0) ? bQ : bK;
    const int arow0 = row0 & 511;

    float4 a_r[2], w_r[4];

    // loaders: float4 along k; 100 % 4 == 0 so float4 never straddles ke
    auto fetch = [&](int k0) {
#pragma unroll
        for (int p = 0; p < 2; p++) {
            int idx = p * 128 + tid;
            int ar = idx & 31, kk = k0 + ((idx >> 5) << 2);
            a_r[p] = (kk < ke) ? *(const float4*)&Ap[(arow0 + ar) * D + kk]
                               : make_float4(0.f, 0.f, 0.f, 0.f);
        }
#pragma unroll
        for (int p = 0; p < 4; p++) {
            int idx = p * 128 + tid;
            int wr = idx & 63, kk = k0 + ((idx >> 6) << 2);
            int gc = col0 + wr;
            w_r[p] = (kk < ke && gc < D) ? *(const float4*)&Wp[gc * D + kk]
                                         : make_float4(0.f, 0.f, 0.f, 0.f);
        }
    };
    auto store = [&](int buf) {
#pragma unroll
        for (int p = 0; p < 2; p++) {
            int idx = p * 128 + tid;
            int ar = idx & 31, e = (idx >> 5) << 2;
            A_s[buf][e + 0][ar] = a_r[p].x; A_s[buf][e + 1][ar] = a_r[p].y;
            A_s[buf][e + 2][ar] = a_r[p].z; A_s[buf][e + 3][ar] = a_r[p].w;
        }
#pragma unroll
        for (int p = 0; p < 4; p++) {
            int idx = p * 128 + tid;
            int wr = idx & 63, e = (idx >> 6) << 2;
            W_s[buf][e + 0][wr] = w_r[p].x; W_s[buf][e + 1][wr] = w_r[p].y;
            W_s[buf][e + 2][wr] = w_r[p].z; W_s[buf][e + 3][wr] = w_r[p].w;
        }
    };

    float acc[4][4];
#pragma unroll
    for (int r = 0; r < 4; r++)
#pragma unroll
        for (int c = 0; c < 4; c++) acc[r][c] = 0.f;

    const int NC = 4;                 // 4 chunks of 32 cover the 100-k third
    fetch(ks);
    store(0);
    __syncthreads();

    for (int ch = 0; ch < NC; ch++) {
        const int buf = ch & 1;
        if (ch + 1 < NC) fetch(ks + (ch + 1) * 32);
#pragma unroll
        for (int e = 0; e < 32; e++) {
            float4 av = *(const float4*)&A_s[buf][e][ty * 4];
            float4 wv = *(const float4*)&W_s[buf][e][tx * 4];
            float a4[4] = {av.x, av.y, av.z, av.w};
            float w4[4] = {wv.x, wv.y, wv.z, wv.w};
#pragma unroll
            for (int r = 0; r < 4; r++)
#pragma unroll
                for (int c = 0; c < 4; c++) acc[r][c] += a4[r] * w4[c];
        }
        if (ch + 1 < NC) store(1 - buf);
        __syncthreads();
    }

#pragma unroll
    for (int r = 0; r < 4; r++) {
        int gr = row0 + ty * 4 + r;
#pragma unroll
        for (int c = 0; c < 4; c++) {
            int gcol = col0 + tx * 4 + c;
            if (gcol < D)
                outp[gr * D + gcol] = acc[r][c] + (kh == 0 ? bp[gcol] : 0.f);
        }
    }
}

// ---------------------------------------------------------------------------
// Kernel 1b: deterministic fixed-order sum of the three k-split partials.
// 115200 float4 = 450 x 256. Partials are L2-resident.
// ---------------------------------------------------------------------------
__global__ __launch_bounds__(256) void reduce_kernel()
{
    int idx = blockIdx.x * 256 + threadIdx.x;
    float4 a = ((const float4*)g_p0)[idx];
    float4 b = ((const float4*)g_p1)[idx];
    float4 c = ((const float4*)g_p2)[idx];
    ((float4*)g_qkv)[idx] =
        make_float4((a.x + b.x) + c.x, (a.y + b.y) + c.y,
                    (a.z + b.z) + c.z, (a.w + b.w) + c.w);
}

// ---------------------------------------------------------------------------
// Kernel 2: fused attention — round-10 winner, UNCHANGED (30.9us, DRAM 67%).
// ---------------------------------------------------------------------------
__global__ __launch_bounds__(256, 4) void attn_kernel(
    const float* __restrict__ hL, const float* __restrict__ hR,
    float* __restrict__ out)
{
    __shared__ float q_s[304];
    __shared__ float scores_s[128];
    __shared__ float listw_s[128];
    __shared__ int   listj_s[128];
    __shared__ int   cnt_s;

    const int tid  = threadIdx.x;
    const int lane = tid & 31;
    const int w    = tid >> 5;           // 8 warps
    const int b    = blockIdx.x >> 7;
    const int i    = blockIdx.x & 127;

    const float4* qkv4 = (const float4*)g_qkv;

    // ---- load q_i (L2-hot, tiny) ----
    if (tid < D4) ((float4*)q_s)[tid] = qkv4[(b * T + i) * D4 + tid];
    __syncthreads();

    const float4* q4 = (const float4*)q_s;
    const bool has_c = (lane < D4 - 64);           // lane < 11

    // ---- scoring: scores_j = sum_d (q[d]+hL[b,i,j,d]) * (k[b,j,d]+hR[b,j,i,d])
    const float4* hL4 = (const float4*)hL + (size_t)(b * T + i) * T * D4;
    const float4* hRb = (const float4*)hR + ((size_t)b * T * T + i) * D4;
    const float4* k4b = qkv4 + (Bq * T + b * T) * D4;

#pragma unroll 2
    for (int jj = 0; jj < 16; jj++) {
        const int j = w * 16 + jj;
        const float4* hl = hL4 + j * D4;
        const float4* hr = hRb + (size_t)j * T * D4;
        const float4* kp = k4b + j * D4;

        float4 l0 = hl[lane],      r0 = hr[lane],      k0 = kp[lane];
        float4 l1 = hl[lane + 32], r1 = hr[lane + 32], k1 = kp[lane + 32];
        float4 l2, r2, k2;
        if (has_c) { l2 = hl[lane + 64]; r2 = hr[lane + 64]; k2 = kp[lane + 64]; }

        float4 qa = q4[lane];
        float acc = (qa.x + l0.x) * (k0.x + r0.x) + (qa.y + l0.y) * (k0.y + r0.y)
                  + (qa.z + l0.z) * (k0.z + r0.z) + (qa.w + l0.w) * (k0.w + r0.w);
        float4 qb = q4[lane + 32];
        acc += (qb.x + l1.x) * (k1.x + r1.x) + (qb.y + l1.y) * (k1.y + r1.y)
             + (qb.z + l1.z) * (k1.z + r1.z) + (qb.w + l1.w) * (k1.w + r1.w);
        if (has_c) {
            float4 qc = q4[lane + 64];
            acc += (qc.x + l2.x) * (k2.x + r2.x) + (qc.y + l2.y) * (k2.y + r2.y)
                 + (qc.z + l2.z) * (k2.z + r2.z) + (qc.w + l2.w) * (k2.w + r2.w);
        }
#pragma unroll
        for (int o = 16; o > 0; o >>= 1)
            acc += __shfl_xor_sync(0xffffffffu, acc, o);
        if (lane == 0) scores_s[j] = acc;
    }
    __syncthreads();

    // ---- p = softmax(scores); attn = softmax(1000*p); clip is a no-op.
    // p_max = 1/sum exactly (max exp term is 1): 1000*(p-p_max) = 1000*inv*(e-1)
    // Build an ORDERED compact list of significant j (deterministic).
    if (w == 0) {
        float s0 = scores_s[lane],      s1 = scores_s[lane + 32];
        float s2 = scores_s[lane + 64], s3 = scores_s[lane + 96];
        float m = fmaxf(fmaxf(s0, s1), fmaxf(s2, s3));
#pragma unroll
        for (int o = 16; o > 0; o >>= 1)
            m = fmaxf(m, __shfl_xor_sync(0xffffffffu, m, o));
        float e0 = expf(s0 - m), e1 = expf(s1 - m);
        float e2 = expf(s2 - m), e3 = expf(s3 - m);
        float sum = e0 + e1 + e2 + e3;
#pragma unroll
        for (int o = 16; o > 0; o >>= 1)
            sum += __shfl_xor_sync(0xffffffffu, sum, o);
        float inv = 1.f / sum;
        float a0 = expf(1000.f * inv * (e0 - 1.f));
        float a1 = expf(1000.f * inv * (e1 - 1.f));
        float a2 = expf(1000.f * inv * (e2 - 1.f));
        float a3 = expf(1000.f * inv * (e3 - 1.f));
        float sum2 = a0 + a1 + a2 + a3;
#pragma unroll
        for (int o = 16; o > 0; o >>= 1)
            sum2 += __shfl_xor_sync(0xffffffffu, sum2, o);
        float inv2 = 1.f / sum2;

        float av[4] = {a0 * inv2, a1 * inv2, a2 * inv2, a3 * inv2};
        int base = 0;
#pragma unroll
        for (int qd = 0; qd < 4; qd++) {
            bool f = av[qd] > 1e-12f;
            unsigned mask = __ballot_sync(0xffffffffu, f);
            int pos = base + __popc(mask & ((1u << lane) - 1u));
            if (f) { listj_s[pos] = qd * 32 + lane; listw_s[pos] = av[qd]; }
            base += __popc(mask);
        }
        if (lane == 0) cnt_s = base;
    }
    __syncthreads();

    // ---- output: out[b,i,d] = sum over significant j of a_j*(v[j,d]+hR[j,i,d])
    const float* vg  = g_qkv + (size_t)(2 * Bq * T + b * T) * D;
    const float* hRs = hR + ((size_t)b * T * T + i) * D;
    const int cnt = cnt_s;
#pragma unroll
    for (int rep = 0; rep < 2; rep++) {
        int d = tid + rep * 256;
        if (d < D) {
            float acc = 0.f;
            for (int t = 0; t < cnt; t++) {
                int   j = listj_s[t];
                float a = listw_s[t];
                acc += a * (vg[j * D + d] + hRs[(size_t)j * T * D + d]);
            }
            out[(b * T + i) * D + d] = acc;
        }
    }
}

// ---------------------------------------------------------------------------
extern "C" void kernel_launch(void* const* d_in, const int* in_sizes, int n_in,
                              void* d_out, int out_size)
{
    const float* query = (const float*)d_in[0];
    const float* key   = (const float*)d_in[1];
    const float* value = (const float*)d_in[2];
    const float* hL    = (const float*)d_in[3];
    const float* hR    = (const float*)d_in[4];
    const float* WQ    = (const float*)d_in[5];
    const float* bQ    = (const float*)d_in[6];
    const float* WK    = (const float*)d_in[7];
    const float* bK    = (const float*)d_in[8];
    float* out = (float*)d_out;

    proj_kernel<<<dim3(5, 48, 3), 128>>>(query, key, value, WQ, bQ, WK, bK);
    reduce_kernel<<<450, 256>>>();
    attn_kernel<<<Bq * T, 256>>>(hL, hR, out);
}